// round 15
// baseline (speedup 1.0000x reference)
#include <cuda_runtime.h>

#define Ww 112
#define NP (112*112)
#define NCH 64
#define G4 28                 // float4 groups per row

// per-channel precomputed params:
// [0..4]=rk, [5..9]=ck, [10]=sigma^p, [11]=weight, [12]=bias,
// [13]=p, [14]=mode (0/1/2), [15]=uni (0/1)
__device__ float g_cp[NCH][16];

__device__ __forceinline__ float rcpa(float x) {
    float y; asm("rcp.approx.f32 %0, %1;" : "=f"(y) : "f"(x)); return y;
}

__device__ __forceinline__ float4 pw4(float4 v, float p, bool p2) {
    float4 r;
    if (p2) { r.x=v.x*v.x; r.y=v.y*v.y; r.z=v.z*v.z; r.w=v.w*v.w; }
    else    { r.x=__powf(v.x,p); r.y=__powf(v.y,p);
              r.z=__powf(v.z,p); r.w=__powf(v.w,p); }
    return r;
}

// 4 outputs with ONE MUFU.RCP
__device__ __forceinline__ float4 norm4v(float4 n, float d0, float d1,
                                         float d2, float d3,
                                         float wgt, float bs) {
    const float d01 = d0*d1, d23 = d2*d3;
    const float r   = rcpa(d01*d23);
    const float r01 = r*d23, r23 = r*d01;
    float4 o;
    o.x = fmaf(wgt*n.x, r01*d1, bs);
    o.y = fmaf(wgt*n.y, r01*d0, bs);
    o.z = fmaf(wgt*n.z, r23*d3, bs);
    o.w = fmaf(wgt*n.w, r23*d2, bs);
    return o;
}

// ---- one-time per-channel parameter derivation (64 threads total) ----
__global__ void bionorm_setup(const float* __restrict__ sigma,
                              const float* __restrict__ pow_p,
                              const float* __restrict__ ker,
                              const float* __restrict__ weight,
                              const float* __restrict__ bias)
{
    const int c = blockIdx.x * blockDim.x + threadIdx.x;
    if (c >= NCH) return;

    const float* kerg = ker + c * 25;
    float kc[25];
#pragma unroll
    for (int i = 0; i < 25; i++) kc[i] = kerg[i];

    float maxa = 0.0f, best = -1.0f; int pi = 0;
#pragma unroll
    for (int i = 0; i < 25; i++) {
        const float a = fabsf(kc[i]);
        maxa = fmaxf(maxa, a);
        if (a > best) { best = a; pi = i; }
    }
    const int i0 = pi / 5, j0 = pi - i0 * 5;

    float rk[5], ck[5];
    float mode = 2.0f, uni = 0.0f;
    if (maxa > 0.0f) {
        const float inv = 1.0f / kc[pi];
#pragma unroll
        for (int i = 0; i < 5; i++) rk[i] = kc[i*5 + j0] * inv;
#pragma unroll
        for (int j = 0; j < 5; j++) ck[j] = kc[i0*5 + j];
        bool sep = true;
        const float tol = 1e-6f * maxa;
#pragma unroll
        for (int i = 0; i < 5; i++)
#pragma unroll
            for (int j = 0; j < 5; j++)
                if (fabsf(fmaf(-rk[i], ck[j], kc[i*5 + j])) > tol) sep = false;
        if (sep) {
            bool unit = true;
#pragma unroll
            for (int i = 0; i < 5; i++)
                if (fabsf(rk[i] - 1.0f) > 1e-6f) unit = false;
            mode = unit ? 0.0f : 1.0f;
            bool u = true;
            const float utol = 1e-6f * fabsf(ck[0]);
#pragma unroll
            for (int j = 1; j < 5; j++)
                if (fabsf(ck[j] - ck[0]) > utol) u = false;
            uni = u ? 1.0f : 0.0f;
        }
    } else {
#pragma unroll
        for (int i = 0; i < 5; i++) { rk[i] = 1.0f; ck[i] = 0.0f; }
        mode = 0.0f; uni = 1.0f;
    }

    const float p   = pow_p[c];
    const float sgm = sigma[c];
    const float sp  = (p == 2.0f) ? sgm*sgm : __powf(sgm, p);

    float* o = g_cp[c];
#pragma unroll
    for (int i = 0; i < 5; i++) o[i]     = rk[i];
#pragma unroll
    for (int j = 0; j < 5; j++) o[5 + j] = ck[j];
    o[10] = sp;       o[11] = weight[c]; o[12] = bias[c];
    o[13] = p;        o[14] = mode;      o[15] = uni;
}

__global__ __launch_bounds__(128, 10)
void bionorm_kernel(const float* __restrict__ x,
                    const float* __restrict__ ker,
                    float* __restrict__ out)
{
    const int bid   = blockIdx.x;
    const int plane = bid >> 1;             // b*C + c
    const int half  = bid & 1;
    const int c     = plane & (NCH - 1);
    const int warp  = threadIdx.x >> 5;     // 0..3
    const int lane  = threadIdx.x & 31;
    const int xl    = min(lane, 27);        // owned float4 group
    const bool act  = lane < 28;

    const float4* __restrict__ xp4 =
        reinterpret_cast<const float4*>(x + (size_t)plane * NP);
    float4* __restrict__ po4 =
        reinterpret_cast<float4*>(out + (size_t)plane * NP);

    // ---- fetch precomputed per-channel params (4 broadcast LDG.128) ----
    const float4* cp4 = reinterpret_cast<const float4*>(g_cp[c]);
    const float4 q0 = __ldg(cp4 + 0);   // rk0..rk3
    const float4 q1 = __ldg(cp4 + 1);   // rk4, ck0, ck1, ck2
    const float4 q2 = __ldg(cp4 + 2);   // ck3, ck4, sp, wgt
    const float4 q3 = __ldg(cp4 + 3);   // bs, p, mode, uni

    float rk[5];
    rk[0]=q0.x; rk[1]=q0.y; rk[2]=q0.z; rk[3]=q0.w; rk[4]=q1.x;
    const float k0=q1.y, k1=q1.z, k2=q1.w, k3=q2.x, k4=q2.y;
    const float sp=q2.z, wgt=q2.w, bs=q3.x, p=q3.y;
    const int  mode = (int)q3.z;
    const bool uni  = (q3.w != 0.0f);
    const bool p2   = (p == 2.0f);
    const float w25 = k0;

    const int y0 = half * 56 + warp * 14;     // this warp's 14-row strip
    int cy = min(max(y0, 2), 109);

    float t0 = 0, t1 = 0, t2 = 0, t3 = 0;     // vertical column sums
    if (mode == 0) {
#pragma unroll
        for (int rr = 0; rr < 5; rr++) {
            float4 q = pw4(xp4[(cy - 2 + rr) * G4 + xl], p, p2);
            t0 += q.x; t1 += q.y; t2 += q.z; t3 += q.w;
        }
    }

#pragma unroll 2
    for (int y = y0; y < y0 + 14; y++) {
        const int cyn = min(max(y, 2), 109);
        float d0, d1, d2, d3;

        if (mode < 2) {
            if (mode == 0) {
                if (cyn != cy) {               // warp-uniform branch
                    float4 e = pw4(xp4[(cyn + 2) * G4 + xl], p, p2);
                    float4 l = pw4(xp4[(cyn - 3) * G4 + xl], p, p2);
                    t0 += e.x - l.x; t1 += e.y - l.y;
                    t2 += e.z - l.z; t3 += e.w - l.w;
                    cy = cyn;
                }
            } else {                            // mode 1: rk-weighted rebuild
                t0 = t1 = t2 = t3 = 0.0f;
#pragma unroll
                for (int rr = 0; rr < 5; rr++) {
                    float4 q = pw4(xp4[(cyn - 2 + rr) * G4 + xl], p, p2);
                    const float w = rk[rr];
                    t0 = fmaf(w, q.x, t0); t1 = fmaf(w, q.y, t1);
                    t2 = fmaf(w, q.z, t2); t3 = fmaf(w, q.w, t3);
                }
            }

            // halo columns from neighbor lanes
            const float am2 = __shfl_up_sync(0xFFFFFFFFu, t2, 1);
            const float am1 = __shfl_up_sync(0xFFFFFFFFu, t3, 1);
            const float a4  = __shfl_down_sync(0xFFFFFFFFu, t0, 1);
            const float a5  = __shfl_down_sync(0xFFFFFFFFu, t1, 1);

            float h0, h1, h2, h3;
            if (uni) {                          // sliding plain 5-sums
                h0 = ((am2 + am1) + (t0 + t1)) + t2;
                h1 = h0 - am2 + t3;
                h2 = h1 - am1 + a4;
                h3 = h2 - t0 + a5;
            } else {                            // ck-weighted windows
                h0 = k0*am2 + k1*am1 + k2*t0 + k3*t1 + k4*t2;
                h1 = k0*am1 + k1*t0  + k2*t1 + k3*t2 + k4*t3;
                h2 = k0*t0  + k1*t1  + k2*t2 + k3*t3 + k4*a4;
                h3 = k0*t1  + k1*t2  + k2*t3 + k3*a4 + k4*a5;
            }
            if (lane == 0)  { h0 = h2; h1 = h2; }   // x-replicate left
            if (lane == 27) { h2 = h1; h3 = h1; }   // x-replicate right

            if (uni) {
                d0 = fmaf(w25, h0, sp); d1 = fmaf(w25, h1, sp);
                d2 = fmaf(w25, h2, sp); d3 = fmaf(w25, h3, sp);
            } else {
                d0 = sp + h0; d1 = sp + h1; d2 = sp + h2; d3 = sp + h3;
            }
        } else {
            // ---- mode 2: general 25-tap gather (cold, correctness only) ----
            const float* xs = reinterpret_cast<const float*>(xp4);
            const float* kerg = ker + c * 25;
            float dd[4];
#pragma unroll
            for (int j = 0; j < 4; j++) {
                const int cx = min(max(4*xl + j, 2), 109);
                float a = 0.0f;
                for (int rr = 0; rr < 5; rr++)
                    for (int tt = 0; tt < 5; tt++) {
                        float v = __ldg(xs + (cyn-2+rr)*Ww + (cx-2+tt));
                        float xv = p2 ? v*v : __powf(v, p);
                        a = fmaf(__ldg(kerg + rr*5 + tt), xv, a);
                    }
                dd[j] = sp + a;
            }
            d0 = dd[0]; d1 = dd[1]; d2 = dd[2]; d3 = dd[3];
        }

        // numerator (L1-resident reload) + normalize + store
        const float4 n = pw4(xp4[y * G4 + xl], p, p2);
        if (act)
            po4[y * G4 + xl] = norm4v(n, d0, d1, d2, d3, wgt, bs);
    }
}

extern "C" void kernel_launch(void* const* d_in, const int* in_sizes, int n_in,
                              void* d_out, int out_size)
{
    const float* x      = (const float*)d_in[0];
    const float* sigma  = (const float*)d_in[1];
    const float* pow_p  = (const float*)d_in[2];
    const float* ker    = (const float*)d_in[3];
    const float* weight = (const float*)d_in[4];
    const float* bias   = (const float*)d_in[5];
    float* out = (float*)d_out;

    bionorm_setup<<<2, 32>>>(sigma, pow_p, ker, weight, bias);
    bionorm_kernel<<<32 * NCH * 2, 128>>>(x, ker, out);
}

// round 17
// speedup vs baseline: 1.2351x; 1.2351x over previous
#include <cuda_runtime.h>

#define Ww 112
#define NP (112*112)
#define NCH 64
#define G4 28                 // float4 groups per row

// per-channel precomputed params:
// [0..4]=rk, [5..9]=ck, [10]=sigma^p, [11]=weight, [12]=bias,
// [13]=p, [14]=mode (0/1/2), [15]=uni (0/1)
__device__ float g_cp[NCH][16];

__device__ __forceinline__ float rcpa(float x) {
    float y; asm("rcp.approx.f32 %0, %1;" : "=f"(y) : "f"(x)); return y;
}

__device__ __forceinline__ float4 pw4(float4 v, float p, bool p2) {
    float4 r;
    if (p2) { r.x=v.x*v.x; r.y=v.y*v.y; r.z=v.z*v.z; r.w=v.w*v.w; }
    else    { r.x=__powf(v.x,p); r.y=__powf(v.y,p);
              r.z=__powf(v.z,p); r.w=__powf(v.w,p); }
    return r;
}

// 4 outputs with ONE MUFU.RCP
__device__ __forceinline__ float4 norm4v(float4 n, float d0, float d1,
                                         float d2, float d3,
                                         float wgt, float bs) {
    const float d01 = d0*d1, d23 = d2*d3;
    const float r   = rcpa(d01*d23);
    const float r01 = r*d23, r23 = r*d01;
    float4 o;
    o.x = fmaf(wgt*n.x, r01*d1, bs);
    o.y = fmaf(wgt*n.y, r01*d0, bs);
    o.z = fmaf(wgt*n.z, r23*d3, bs);
    o.w = fmaf(wgt*n.w, r23*d2, bs);
    return o;
}

// ---- one-time per-channel parameter derivation ----
__global__ void bionorm_setup(const float* __restrict__ sigma,
                              const float* __restrict__ pow_p,
                              const float* __restrict__ ker,
                              const float* __restrict__ weight,
                              const float* __restrict__ bias)
{
    const int c = blockIdx.x * blockDim.x + threadIdx.x;
    if (c >= NCH) return;

    const float* kerg = ker + c * 25;
    float kc[25];
#pragma unroll
    for (int i = 0; i < 25; i++) kc[i] = kerg[i];

    float maxa = 0.0f, best = -1.0f; int pi = 0;
#pragma unroll
    for (int i = 0; i < 25; i++) {
        const float a = fabsf(kc[i]);
        maxa = fmaxf(maxa, a);
        if (a > best) { best = a; pi = i; }
    }
    const int i0 = pi / 5, j0 = pi - i0 * 5;

    float rk[5], ck[5];
    float mode = 2.0f, uni = 0.0f;
    if (maxa > 0.0f) {
        const float inv = 1.0f / kc[pi];
#pragma unroll
        for (int i = 0; i < 5; i++) rk[i] = kc[i*5 + j0] * inv;
#pragma unroll
        for (int j = 0; j < 5; j++) ck[j] = kc[i0*5 + j];
        bool sep = true;
        const float tol = 1e-6f * maxa;
#pragma unroll
        for (int i = 0; i < 5; i++)
#pragma unroll
            for (int j = 0; j < 5; j++)
                if (fabsf(fmaf(-rk[i], ck[j], kc[i*5 + j])) > tol) sep = false;
        if (sep) {
            bool unit = true;
#pragma unroll
            for (int i = 0; i < 5; i++)
                if (fabsf(rk[i] - 1.0f) > 1e-6f) unit = false;
            mode = unit ? 0.0f : 1.0f;
            bool u = true;
            const float utol = 1e-6f * fabsf(ck[0]);
#pragma unroll
            for (int j = 1; j < 5; j++)
                if (fabsf(ck[j] - ck[0]) > utol) u = false;
            uni = u ? 1.0f : 0.0f;
        }
    } else {
#pragma unroll
        for (int i = 0; i < 5; i++) { rk[i] = 1.0f; ck[i] = 0.0f; }
        mode = 0.0f; uni = 1.0f;
    }

    const float p   = pow_p[c];
    const float sgm = sigma[c];
    const float sp  = (p == 2.0f) ? sgm*sgm : __powf(sgm, p);

    float* o = g_cp[c];
#pragma unroll
    for (int i = 0; i < 5; i++) o[i]     = rk[i];
#pragma unroll
    for (int j = 0; j < 5; j++) o[5 + j] = ck[j];
    o[10] = sp;       o[11] = weight[c]; o[12] = bias[c];
    o[13] = p;        o[14] = mode;      o[15] = uni;
}

__global__ __launch_bounds__(128, 9)
void bionorm_kernel(const float* __restrict__ x,
                    const float* __restrict__ ker,
                    float* __restrict__ out)
{
    const int bid   = blockIdx.x;
    const int plane = bid >> 1;             // b*C + c
    const int half  = bid & 1;
    const int c     = plane & (NCH - 1);
    const int warp  = threadIdx.x >> 5;     // 0..3
    const int lane  = threadIdx.x & 31;
    const int xl    = min(lane, 27);        // owned float4 group
    const bool act  = lane < 28;

    const float4* __restrict__ xp4 =
        reinterpret_cast<const float4*>(x + (size_t)plane * NP);
    float4* __restrict__ po4 =
        reinterpret_cast<float4*>(out + (size_t)plane * NP);

    // ---- fetch precomputed per-channel params (4 broadcast LDG.128) ----
    const float4* cp4 = reinterpret_cast<const float4*>(g_cp[c]);
    const float4 q0 = __ldg(cp4 + 0);   // rk0..rk3
    const float4 q1 = __ldg(cp4 + 1);   // rk4, ck0, ck1, ck2
    const float4 q2 = __ldg(cp4 + 2);   // ck3, ck4, sp, wgt
    const float4 q3 = __ldg(cp4 + 3);   // bs, p, mode, uni

    const float k0=q1.y, k1=q1.z, k2=q1.w, k3=q2.x, k4=q2.y;
    const float sp=q2.z, wgt=q2.w, bs=q3.x, p=q3.y;
    const int  mode = (int)q3.z;
    const bool uni  = (q3.w != 0.0f);
    const bool p2   = (p == 2.0f);
    const float w25 = k0;

    const int y0 = half * 56 + warp * 14;     // this warp's 14-row strip
    int cy = min(max(y0, 2), 109);

    auto pwl = [&](int row) -> float4 {
        return pw4(__ldg(&xp4[row * G4 + xl]), p, p2);
    };

    if (mode == 0) {
        // ===== hot path: vertical slide + 2-slot numerator parity ring =====
        float t0 = 0, t1 = 0, t2 = 0, t3 = 0;
        float4 nA, nB;                        // numerators for even/odd y
        const int io = y0 - (cy - 2);         // window index of row y0 (0 or 2)
#pragma unroll
        for (int rr = 0; rr < 5; rr++) {
            const float4 q = pwl(cy - 2 + rr);
            t0 += q.x; t1 += q.y; t2 += q.z; t3 += q.w;
            if (rr == io)     nA = q;         // row y0   (y0 even)
            if (rr == io + 1) nB = q;         // row y0+1
        }

        auto step = [&](int y, float4& slot) {
            const float4 num = slot;          // numerator = x^p[row y]
            const int cyn = min(max(y, 2), 109);
            if (cyn != cy) {                  // warp-uniform slide
                const float4 e = pwl(cyn + 2);
                const float4 l = pwl(cyn - 3);
                t0 += e.x - l.x; t1 += e.y - l.y;
                t2 += e.z - l.z; t3 += e.w - l.w;
                cy = cyn;
                slot = e;                     // row y+2: numerator for y+2
            } else {                          // edge rows: explicit refill
                slot = pwl(min(y + 2, 111));
            }

            const float am2 = __shfl_up_sync(0xFFFFFFFFu, t2, 1);
            const float am1 = __shfl_up_sync(0xFFFFFFFFu, t3, 1);
            const float a4  = __shfl_down_sync(0xFFFFFFFFu, t0, 1);
            const float a5  = __shfl_down_sync(0xFFFFFFFFu, t1, 1);

            float h0, h1, h2, h3;
            if (uni) {                        // sliding plain 5-sums
                h0 = ((am2 + am1) + (t0 + t1)) + t2;
                h1 = h0 - am2 + t3;
                h2 = h1 - am1 + a4;
                h3 = h2 - t0 + a5;
            } else {                          // ck-weighted windows
                h0 = k0*am2 + k1*am1 + k2*t0 + k3*t1 + k4*t2;
                h1 = k0*am1 + k1*t0  + k2*t1 + k3*t2 + k4*t3;
                h2 = k0*t0  + k1*t1  + k2*t2 + k3*t3 + k4*a4;
                h3 = k0*t1  + k1*t2  + k2*t3 + k3*a4 + k4*a5;
            }
            if (lane == 0)  { h0 = h2; h1 = h2; }   // x-replicate left
            if (lane == 27) { h2 = h1; h3 = h1; }   // x-replicate right

            float d0, d1, d2, d3;
            if (uni) {
                d0 = fmaf(w25, h0, sp); d1 = fmaf(w25, h1, sp);
                d2 = fmaf(w25, h2, sp); d3 = fmaf(w25, h3, sp);
            } else {
                d0 = sp + h0; d1 = sp + h1; d2 = sp + h2; d3 = sp + h3;
            }
            if (act)
                po4[y * G4 + xl] = norm4v(num, d0, d1, d2, d3, wgt, bs);
        };

#pragma unroll
        for (int i = 0; i < 14; i += 2) {     // static parity: A even, B odd
            step(y0 + i,     nA);
            step(y0 + i + 1, nB);
        }
        return;
    }

    // ===== cold paths (modes 1, 2) =====
    float rk[5];
    rk[0]=q0.x; rk[1]=q0.y; rk[2]=q0.z; rk[3]=q0.w; rk[4]=q1.x;

#pragma unroll 1
    for (int y = y0; y < y0 + 14; y++) {
        const int cyn = min(max(y, 2), 109);
        float d0, d1, d2, d3;

        if (mode == 1) {
            float t0 = 0, t1 = 0, t2 = 0, t3 = 0;
#pragma unroll
            for (int rr = 0; rr < 5; rr++) {
                const float4 q = pwl(cyn - 2 + rr);
                const float w = rk[rr];
                t0 = fmaf(w, q.x, t0); t1 = fmaf(w, q.y, t1);
                t2 = fmaf(w, q.z, t2); t3 = fmaf(w, q.w, t3);
            }
            const float am2 = __shfl_up_sync(0xFFFFFFFFu, t2, 1);
            const float am1 = __shfl_up_sync(0xFFFFFFFFu, t3, 1);
            const float a4  = __shfl_down_sync(0xFFFFFFFFu, t0, 1);
            const float a5  = __shfl_down_sync(0xFFFFFFFFu, t1, 1);
            float h0 = k0*am2 + k1*am1 + k2*t0 + k3*t1 + k4*t2;
            float h1 = k0*am1 + k1*t0  + k2*t1 + k3*t2 + k4*t3;
            float h2 = k0*t0  + k1*t1  + k2*t2 + k3*t3 + k4*a4;
            float h3 = k0*t1  + k1*t2  + k2*t3 + k3*a4 + k4*a5;
            if (lane == 0)  { h0 = h2; h1 = h2; }
            if (lane == 27) { h2 = h1; h3 = h1; }
            d0 = sp + h0; d1 = sp + h1; d2 = sp + h2; d3 = sp + h3;
        } else {
            const float* xs = reinterpret_cast<const float*>(xp4);
            const float* kerg = ker + c * 25;
            float dd[4];
#pragma unroll
            for (int j = 0; j < 4; j++) {
                const int cx = min(max(4*xl + j, 2), 109);
                float a = 0.0f;
                for (int rr = 0; rr < 5; rr++)
                    for (int tt = 0; tt < 5; tt++) {
                        float v = __ldg(xs + (cyn-2+rr)*Ww + (cx-2+tt));
                        float xv = p2 ? v*v : __powf(v, p);
                        a = fmaf(__ldg(kerg + rr*5 + tt), xv, a);
                    }
                dd[j] = sp + a;
            }
            d0 = dd[0]; d1 = dd[1]; d2 = dd[2]; d3 = dd[3];
        }

        const float4 n = pwl(y);
        if (act)
            po4[y * G4 + xl] = norm4v(n, d0, d1, d2, d3, wgt, bs);
    }
}

extern "C" void kernel_launch(void* const* d_in, const int* in_sizes, int n_in,
                              void* d_out, int out_size)
{
    const float* x      = (const float*)d_in[0];
    const float* sigma  = (const float*)d_in[1];
    const float* pow_p  = (const float*)d_in[2];
    const float* ker    = (const float*)d_in[3];
    const float* weight = (const float*)d_in[4];
    const float* bias   = (const float*)d_in[5];
    float* out = (float*)d_out;

    bionorm_setup<<<2, 32>>>(sigma, pow_p, ker, weight, bias);
    bionorm_kernel<<<32 * NCH * 2, 128>>>(x, ker, out);
}